// round 10
// baseline (speedup 1.0000x reference)
#include <cuda_runtime.h>
#include <cuda_bf16.h>
#include <math.h>
#include <stdint.h>

// ---------------- dimensions ----------------
#define B_   8
#define T_   1024
#define BT   8192           // B_*T_
#define IN_  512
#define D_   1024
#define I_   2048
#define N_   64
#define H_   16
#define P_   128
#define K_   3
#define L_   4
#define OUT_ 512
#define CB_  1024
#define CONV_ 2176          // I_ + 2*N_
#define PROJ_ 4240          // I_ + CONV_ + H_

// ---------------- device scratch (no allocation allowed) ----------------
__device__ float g_h[(size_t)BT * D_];
__device__ float g_hn[(size_t)BT * D_];
__device__ float g_proj[(size_t)BT * PROJ_];
__device__ float g_conv[(size_t)BT * CONV_];
__device__ float g_dt[(size_t)BT * H_];
__device__ float g_y[2][(size_t)BT * I_];   // two N-half partials

// ---------------- helpers ----------------
__device__ __forceinline__ float block_reduce_sum(float v) {
    __shared__ float red[32];
    int lane = threadIdx.x & 31, wid = threadIdx.x >> 5;
    #pragma unroll
    for (int o = 16; o; o >>= 1) v += __shfl_xor_sync(0xffffffffu, v, o);
    if (lane == 0) red[wid] = v;
    __syncthreads();
    int nw = blockDim.x >> 5;
    v = (threadIdx.x < (unsigned)nw) ? red[threadIdx.x] : 0.f;
    if (wid == 0) {
        #pragma unroll
        for (int o = 16; o; o >>= 1) v += __shfl_xor_sync(0xffffffffu, v, o);
        if (lane == 0) red[0] = v;
    }
    __syncthreads();
    return red[0];
}

__device__ __forceinline__ float siluf(float x) {
    return x / (1.f + __expf(-x));
}

// split two fp32 values into packed bf16x2 hi + bf16x2 lo (v0 in low half)
__device__ __forceinline__ void split_bf16_pair(float v0, float v1, uint32_t& hi, uint32_t& lo) {
    __nv_bfloat162 h = __floats2bfloat162_rn(v0, v1);
    float h0 = __bfloat162float(h.x);
    float h1 = __bfloat162float(h.y);
    __nv_bfloat162 l = __floats2bfloat162_rn(v0 - h0, v1 - h1);
    hi = *reinterpret_cast<uint32_t*>(&h);
    lo = *reinterpret_cast<uint32_t*>(&l);
}

__device__ __forceinline__ void mma_bf16(float* d, const uint32_t* a, const uint32_t* b) {
    asm volatile(
        "mma.sync.aligned.m16n8k16.row.col.f32.bf16.bf16.f32 "
        "{%0,%1,%2,%3}, {%4,%5,%6,%7}, {%8,%9}, {%0,%1,%2,%3};"
        : "+f"(d[0]), "+f"(d[1]), "+f"(d[2]), "+f"(d[3])
        : "r"(a[0]), "r"(a[1]), "r"(a[2]), "r"(a[3]), "r"(b[0]), "r"(b[1]));
}

// ---------------- split-bf16 (bf16x3) tensor-core GEMM: C = A @ B (+bias)(+=C)
// Tiles: BM=128, BN=128, BK=32. 256 threads = 8 warps (4x2), warp tile 32x64
// (best-measured shape, R7). Occupancy 2 CTAs/SM (128-reg cap) + TRIPLE
// buffering: LDG for chunk kt+2 issues at iter kt, overlapping across CTAs.
// Smem packed bf16x2 (k,k+1) pair format:
// A: [128][ASTR2=20] u32 -> frag banks 20*gid+t4 all distinct.
// B: [16][BSTR2=136] u32 -> frag banks 8*t4+gid all distinct.
#define ASTR2 20
#define BSTR2 136
#define A_BUF (128 * ASTR2)
#define B_BUF (16 * BSTR2)
#define NBUF 3
#define GEMM_SMEM (NBUF * 2 * (A_BUF + B_BUF) * 4)   // 113,664 B

__global__ void __launch_bounds__(256, 2) gemm_tc(
    const float* __restrict__ A, const float* __restrict__ Bm,
    float* __restrict__ C, int M, int N, int K,
    const float* __restrict__ bias, int accum)
{
    extern __shared__ uint32_t smem[];
    uint32_t* AsH = smem;                     // [NBUF][A_BUF]
    uint32_t* AsL = AsH + NBUF * A_BUF;
    uint32_t* BsH = AsL + NBUF * A_BUF;       // [NBUF][B_BUF]
    uint32_t* BsL = BsH + NBUF * B_BUF;

    const int tid = threadIdx.x;
    const int lane = tid & 31;
    const int warp = tid >> 5;
    const int warpM = warp >> 1;              // 0..3
    const int warpN = warp & 1;               // 0..1
    const int gid = lane >> 2;                // 0..7
    const int tid4 = lane & 3;                // 0..3

    const int m0 = blockIdx.y * 128;
    const int n0 = blockIdx.x * 128;

    // A loader: row = tid>>3 (+32i), k4 = (tid&7)*4  (coalesced 128B rows)
    const int a_row = tid >> 3;
    const int a_k4 = (tid & 7) * 4;
    // B loader: warp handles kp = warp, warp+8; lane covers n4 = lane*4
    const int b_n4 = lane * 4;

    float acc[2][8][4];
    #pragma unroll
    for (int i = 0; i < 2; i++)
        #pragma unroll
        for (int j = 0; j < 8; j++)
            #pragma unroll
            for (int c = 0; c < 4; c++) acc[i][j][c] = 0.f;

    float4 pa[4];
    float4 pb[4];                             // [kp-slot][2 k-rows]
    const bool edge = (n0 + 128 > N);

    auto loadAB = [&](int kt) {
        const int kbase = kt * 32;
        #pragma unroll
        for (int i = 0; i < 4; i++)
            pa[i] = *reinterpret_cast<const float4*>(
                A + (size_t)(m0 + a_row + 32 * i) * K + kbase + a_k4);
        const int n = n0 + b_n4;
        #pragma unroll
        for (int i = 0; i < 2; i++) {
            const int kp = warp + 8 * i;
            #pragma unroll
            for (int r = 0; r < 2; r++) {
                const size_t off = (size_t)(kbase + 2 * kp + r) * N;
                float4 v;
                if (!edge) {
                    v = *reinterpret_cast<const float4*>(Bm + off + n);
                } else {
                    v.x = (n + 0 < N) ? Bm[off + n + 0] : 0.f;
                    v.y = (n + 1 < N) ? Bm[off + n + 1] : 0.f;
                    v.z = (n + 2 < N) ? Bm[off + n + 2] : 0.f;
                    v.w = (n + 3 < N) ? Bm[off + n + 3] : 0.f;
                }
                pb[2 * i + r] = v;
            }
        }
    };

    auto smemStore = [&](int buf) {
        uint32_t* ah = AsH + buf * A_BUF;
        uint32_t* al = AsL + buf * A_BUF;
        #pragma unroll
        for (int i = 0; i < 4; i++) {
            const int m = a_row + 32 * i;
            uint2 h2, l2;
            split_bf16_pair(pa[i].x, pa[i].y, h2.x, l2.x);
            split_bf16_pair(pa[i].z, pa[i].w, h2.y, l2.y);
            const int idx = m * ASTR2 + (a_k4 >> 1);
            *reinterpret_cast<uint2*>(ah + idx) = h2;
            *reinterpret_cast<uint2*>(al + idx) = l2;
        }
        uint32_t* bh = BsH + buf * B_BUF;
        uint32_t* bl = BsL + buf * B_BUF;
        #pragma unroll
        for (int i = 0; i < 2; i++) {
            const int kp = warp + 8 * i;
            const float4 r0 = pb[2 * i];      // k = 2kp
            const float4 r1 = pb[2 * i + 1];  // k = 2kp+1
            uint4 h4, l4;
            split_bf16_pair(r0.x, r1.x, h4.x, l4.x);
            split_bf16_pair(r0.y, r1.y, h4.y, l4.y);
            split_bf16_pair(r0.z, r1.z, h4.z, l4.z);
            split_bf16_pair(r0.w, r1.w, h4.w, l4.w);
            const int idx = kp * BSTR2 + b_n4;
            *reinterpret_cast<uint4*>(bh + idx) = h4;
            *reinterpret_cast<uint4*>(bl + idx) = l4;
        }
    };

    auto compute = [&](int buf) {
        const uint32_t* ah_s = AsH + buf * A_BUF;
        const uint32_t* al_s = AsL + buf * A_BUF;
        const uint32_t* bh_s = BsH + buf * B_BUF;
        const uint32_t* bl_s = BsL + buf * B_BUF;
        #pragma unroll
        for (int ks = 0; ks < 2; ks++) {
            const int kp0 = ks * 8;
            uint32_t ah[2][4], al[2][4], bh[8][2], bl[8][2];
            #pragma unroll
            for (int mf = 0; mf < 2; mf++) {
                const int m = warpM * 32 + mf * 16 + gid;
                const int i0 = m * ASTR2 + kp0 + tid4;
                const int i1 = (m + 8) * ASTR2 + kp0 + tid4;
                ah[mf][0] = ah_s[i0];     al[mf][0] = al_s[i0];
                ah[mf][1] = ah_s[i1];     al[mf][1] = al_s[i1];
                ah[mf][2] = ah_s[i0 + 4]; al[mf][2] = al_s[i0 + 4];
                ah[mf][3] = ah_s[i1 + 4]; al[mf][3] = al_s[i1 + 4];
            }
            #pragma unroll
            for (int nf = 0; nf < 8; nf++) {
                const int n = warpN * 64 + nf * 8 + gid;
                const int i0 = (kp0 + tid4) * BSTR2 + n;
                const int i1 = (kp0 + tid4 + 4) * BSTR2 + n;
                bh[nf][0] = bh_s[i0]; bl[nf][0] = bl_s[i0];
                bh[nf][1] = bh_s[i1]; bl[nf][1] = bl_s[i1];
            }
            #pragma unroll
            for (int mf = 0; mf < 2; mf++)
                #pragma unroll
                for (int nf = 0; nf < 8; nf++) {
                    mma_bf16(acc[mf][nf], ah[mf], bh[nf]);
                    mma_bf16(acc[mf][nf], al[mf], bh[nf]);
                    mma_bf16(acc[mf][nf], ah[mf], bl[nf]);
                }
        }
    };

    const int nk = K >> 5;
    loadAB(0);
    smemStore(0);
    if (nk > 1) { loadAB(1); smemStore(1); }
    __syncthreads();
    for (int kt = 0; kt < nk; kt++) {
        if (kt + 2 < nk) loadAB(kt + 2);
        compute(kt % NBUF);
        if (kt + 2 < nk) smemStore((kt + 2) % NBUF);
        __syncthreads();
    }

    // epilogue: C rows m, cols n..n+1 (float2)
    #pragma unroll
    for (int mf = 0; mf < 2; mf++) {
        #pragma unroll
        for (int nf = 0; nf < 8; nf++) {
            const int n = n0 + warpN * 64 + nf * 8 + tid4 * 2;
            if (n >= N) continue;
            float bv0 = 0.f, bv1 = 0.f;
            if (bias) { bv0 = bias[n]; bv1 = bias[n + 1]; }
            #pragma unroll
            for (int h = 0; h < 2; h++) {
                const int m = m0 + warpM * 32 + mf * 16 + gid + h * 8;
                float v0 = acc[mf][nf][2 * h]     + bv0;
                float v1 = acc[mf][nf][2 * h + 1] + bv1;
                const size_t idx = (size_t)m * N + n;
                if (accum) { v0 += C[idx]; v1 += C[idx + 1]; }
                C[idx] = v0;
                C[idx + 1] = v1;
            }
        }
    }
}

// ---------------- rmsnorm (row length ncol) ----------------
__global__ void rmsnorm_kernel(const float* __restrict__ x, const float* __restrict__ w,
                               float* __restrict__ out, int ncol)
{
    int row = blockIdx.x;
    const float* xr = x + (size_t)row * ncol;
    float ss = 0.f;
    for (int i = threadIdx.x; i < ncol; i += blockDim.x) {
        float v = xr[i];
        ss += v * v;
    }
    float tot = block_reduce_sum(ss);
    float r = rsqrtf(tot / (float)ncol + 1e-6f);
    for (int i = threadIdx.x; i < ncol; i += blockDim.x)
        out[(size_t)row * ncol + i] = xr[i] * r * w[i];
}

// ---------------- causal depthwise conv (K=3) + silu (2-D grid) ----------------
__global__ void conv_kernel(const float* __restrict__ proj, const float* __restrict__ w,
                            const float* __restrict__ bias, float* __restrict__ out)
{
    int c = blockIdx.x * 256 + threadIdx.x;
    if (c >= CONV_) return;
    int row = blockIdx.y;
    int t = row & (T_ - 1);
    const float* pr = proj + (size_t)row * PROJ_ + I_ + c;
    float acc = bias[c] + pr[0] * w[2 * CONV_ + c];
    if (t >= 1) acc += pr[-(ptrdiff_t)PROJ_] * w[CONV_ + c];
    if (t >= 2) acc += pr[-2 * (ptrdiff_t)PROJ_] * w[c];
    out[(size_t)row * CONV_ + c] = siluf(acc);
}

// ---------------- dt = softplus(proj_dt + dt_bias) ----------------
__global__ void dt_kernel(const float* __restrict__ proj, const float* __restrict__ dtb,
                          float* __restrict__ out)
{
    int idx = blockIdx.x * 256 + threadIdx.x;
    if (idx >= BT * H_) return;
    int h = idx & (H_ - 1);
    int row = idx >> 4;
    float v = proj[(size_t)row * PROJ_ + I_ + CONV_ + h] + dtb[h];
    out[idx] = (v > 20.f) ? v : log1pf(__expf(v));
}

// ---------------- sequential SSM scan: one CTA per (b,h,n-half) ----------------
__global__ void __launch_bounds__(128) scan_kernel(
    const float* __restrict__ conv,   // [BT, CONV_]
    const float* __restrict__ dt,     // [BT, H_]
    const float* __restrict__ A_log,  // [H_]
    const float* __restrict__ Dv,     // [H_]
    float* __restrict__ y)            // [2][BT, I_] partials
{
    const int half = blockIdx.x >> 7;         // 0/1 -> n in [0,32) or [32,64)
    const int bh = blockIdx.x & 127;
    const int b = bh >> 4;
    const int h = bh & 15;
    const int p = threadIdx.x;
    const int n_off = half * 32;
    __shared__ float sB[32], sC[32];
    float a = -__expf(A_log[h]);
    float dcoef = (half == 0) ? Dv[h] : 0.f;
    float s[32];
    #pragma unroll
    for (int n = 0; n < 32; n++) s[n] = 0.f;

    const float* convb = conv + (size_t)b * T_ * CONV_;
    const float* dtb = dt + (size_t)b * T_ * H_ + h;
    float* yb = y + (size_t)half * BT * I_ + (size_t)b * T_ * I_ + h * P_ + p;

    for (int t = 0; t < T_; t++) {
        const float* crow = convb + (size_t)t * CONV_;
        if (p < 32)       sB[p] = crow[I_ + n_off + p];
        else if (p < 64)  sC[p - 32] = crow[I_ + N_ + n_off + (p - 32)];
        float dtv = dtb[(size_t)t * H_];
        float xv = crow[h * P_ + p];
        __syncthreads();
        float dA = __expf(dtv * a);
        float dtx = dtv * xv;
        float y0 = 0.f, y1 = 0.f, y2 = 0.f, y3 = 0.f;
        #pragma unroll
        for (int n = 0; n < 32; n += 4) {
            s[n]     = s[n]     * dA + dtx * sB[n];     y0 += s[n]     * sC[n];
            s[n + 1] = s[n + 1] * dA + dtx * sB[n + 1]; y1 += s[n + 1] * sC[n + 1];
            s[n + 2] = s[n + 2] * dA + dtx * sB[n + 2]; y2 += s[n + 2] * sC[n + 2];
            s[n + 3] = s[n + 3] * dA + dtx * sB[n + 3]; y3 += s[n + 3] * sC[n + 3];
        }
        yb[(size_t)t * I_] = (y0 + y1) + (y2 + y3) + dcoef * xv;
        __syncthreads();
    }
}

// ---------------- gated rmsnorm: y = rmsnorm((y0+y1) * silu(gate)) * w ---------
__global__ void __launch_bounds__(256) grms_kernel(
    float* __restrict__ yout, const float* __restrict__ y0p, const float* __restrict__ y1p,
    const float* __restrict__ proj, const float* __restrict__ w)
{
    int row = blockIdx.x;
    const float* y0r = y0p + (size_t)row * I_;
    const float* y1r = y1p + (size_t)row * I_;
    const float* gr = proj + (size_t)row * PROJ_;
    float v[8];
    float ss = 0.f;
    #pragma unroll
    for (int k = 0; k < 8; k++) {
        int i = threadIdx.x + k * 256;
        float g = gr[i];
        float vv = (y0r[i] + y1r[i]) * siluf(g);
        v[k] = vv;
        ss += vv * vv;
    }
    float tot = block_reduce_sum(ss);
    float r = rsqrtf(tot * (1.f / (float)I_) + 1e-6f);
    #pragma unroll
    for (int k = 0; k < 8; k++) {
        int i = threadIdx.x + k * 256;
        yout[(size_t)row * I_ + i] = v[k] * r * w[i];
    }
}

// ---------------- host launcher ----------------
extern "C" void kernel_launch(void* const* d_in, const int* in_sizes, int n_in,
                              void* d_out, int out_size)
{
    const float* x        = (const float*)d_in[0];
    const float* in_w     = (const float*)d_in[1];
    const float* in_b     = (const float*)d_in[2];
    const float* norm_w   = (const float*)d_in[3];
    const float* mix_in_w = (const float*)d_in[4];
    const float* conv_w   = (const float*)d_in[5];
    const float* conv_b   = (const float*)d_in[6];
    const float* dt_bias  = (const float*)d_in[7];
    const float* A_log    = (const float*)d_in[8];
    const float* Dvec     = (const float*)d_in[9];
    const float* gnorm_w  = (const float*)d_in[10];
    const float* mix_out_w= (const float*)d_in[11];
    const float* out_w    = (const float*)d_in[12];
    const float* out_b    = (const float*)d_in[13];
    const float* code_w   = (const float*)d_in[14];
    const float* code_b   = (const float*)d_in[15];
    float* out = (float*)d_out;

    float *h, *hn, *proj, *conv, *dtb, *yb;
    cudaGetSymbolAddress((void**)&h,    g_h);
    cudaGetSymbolAddress((void**)&hn,   g_hn);
    cudaGetSymbolAddress((void**)&proj, g_proj);
    cudaGetSymbolAddress((void**)&conv, g_conv);
    cudaGetSymbolAddress((void**)&dtb,  g_dt);
    cudaGetSymbolAddress((void**)&yb,   g_y);
    float* yb0 = yb;
    float* yb1 = yb + (size_t)BT * I_;

    cudaFuncSetAttribute(gemm_tc, cudaFuncAttributeMaxDynamicSharedMemorySize, GEMM_SMEM);

    // h = x @ in_w + in_b
    gemm_tc<<<dim3(D_ / 128, BT / 128), 256, GEMM_SMEM>>>(x, in_w, h, BT, D_, IN_, in_b, 0);

    for (int l = 0; l < L_; l++) {
        rmsnorm_kernel<<<BT, 256>>>(h, norm_w + l * D_, hn, D_);
        gemm_tc<<<dim3((PROJ_ + 127) / 128, BT / 128), 256, GEMM_SMEM>>>(
            hn, mix_in_w + (size_t)l * D_ * PROJ_, proj, BT, PROJ_, D_, nullptr, 0);
        conv_kernel<<<dim3((CONV_ + 255) / 256, BT), 256>>>(
            proj, conv_w + (size_t)l * K_ * CONV_, conv_b + (size_t)l * CONV_, conv);
        dt_kernel<<<(BT * H_ + 255) / 256, 256>>>(proj, dt_bias + l * H_, dtb);
        scan_kernel<<<2 * B_ * H_, 128>>>(conv, dtb, A_log + l * H_, Dvec + l * H_, yb);
        grms_kernel<<<BT, 256>>>(yb0, yb0, yb1, proj, gnorm_w + (size_t)l * I_);
        gemm_tc<<<dim3(D_ / 128, BT / 128), 256, GEMM_SMEM>>>(
            yb0, mix_out_w + (size_t)l * I_ * D_, h, BT, D_, I_, nullptr, 1);
    }

    // heads
    gemm_tc<<<dim3(OUT_ / 128, BT / 128), 256, GEMM_SMEM>>>(h, out_w, out, BT, OUT_, D_, out_b, 0);
    gemm_tc<<<dim3(CB_ / 128, BT / 128), 256, GEMM_SMEM>>>(
        h, code_w, out + (size_t)BT * OUT_, BT, CB_, D_, code_b, 0);
}

// round 12
// speedup vs baseline: 1.1246x; 1.1246x over previous
#include <cuda_runtime.h>
#include <cuda_bf16.h>
#include <math.h>
#include <stdint.h>

// ---------------- dimensions ----------------
#define B_   8
#define T_   1024
#define BT   8192           // B_*T_
#define IN_  512
#define D_   1024
#define I_   2048
#define N_   64
#define H_   16
#define P_   128
#define K_   3
#define L_   4
#define OUT_ 512
#define CB_  1024
#define CONV_ 2176          // I_ + 2*N_
#define PROJ_ 4240          // I_ + CONV_ + H_

// ---------------- device scratch (no allocation allowed) ----------------
__device__ float g_h[(size_t)BT * D_];
__device__ float g_hn[(size_t)BT * D_];
__device__ float g_proj[(size_t)BT * PROJ_];
__device__ float g_conv[(size_t)BT * CONV_];
__device__ float g_dt[(size_t)BT * H_];
__device__ float g_y[2][(size_t)BT * I_];   // two N-half partials

// ---------------- helpers ----------------
__device__ __forceinline__ float block_reduce_sum(float v) {
    __shared__ float red[32];
    int lane = threadIdx.x & 31, wid = threadIdx.x >> 5;
    #pragma unroll
    for (int o = 16; o; o >>= 1) v += __shfl_xor_sync(0xffffffffu, v, o);
    if (lane == 0) red[wid] = v;
    __syncthreads();
    int nw = blockDim.x >> 5;
    v = (threadIdx.x < (unsigned)nw) ? red[threadIdx.x] : 0.f;
    if (wid == 0) {
        #pragma unroll
        for (int o = 16; o; o >>= 1) v += __shfl_xor_sync(0xffffffffu, v, o);
        if (lane == 0) red[0] = v;
    }
    __syncthreads();
    return red[0];
}

__device__ __forceinline__ float siluf(float x) {
    return x / (1.f + __expf(-x));
}

// split two fp32 values into packed bf16x2 hi + bf16x2 lo (v0 in low half)
__device__ __forceinline__ void split_bf16_pair(float v0, float v1, uint32_t& hi, uint32_t& lo) {
    __nv_bfloat162 h = __floats2bfloat162_rn(v0, v1);
    float h0 = __bfloat162float(h.x);
    float h1 = __bfloat162float(h.y);
    __nv_bfloat162 l = __floats2bfloat162_rn(v0 - h0, v1 - h1);
    hi = *reinterpret_cast<uint32_t*>(&h);
    lo = *reinterpret_cast<uint32_t*>(&l);
}

__device__ __forceinline__ void mma_bf16(float* d, const uint32_t* a, const uint32_t* b) {
    asm volatile(
        "mma.sync.aligned.m16n8k16.row.col.f32.bf16.bf16.f32 "
        "{%0,%1,%2,%3}, {%4,%5,%6,%7}, {%8,%9}, {%0,%1,%2,%3};"
        : "+f"(d[0]), "+f"(d[1]), "+f"(d[2]), "+f"(d[3])
        : "r"(a[0]), "r"(a[1]), "r"(a[2]), "r"(a[3]), "r"(b[0]), "r"(b[1]));
}

// ---------------- split-bf16 (bf16x3) tensor-core GEMM: C = A @ B (+bias)(+=C)
// EXACT R7 configuration (best measured): BM=128, BN=128, BK=32, 256 threads
// = 8 warps (4x2), warp tile 32x64, double buffered, split hoisted to store.
// A: [128][ASTR2=20] u32 -> frag banks 20*gid+t4 all distinct.
// B: [16][BSTR2=136] u32 -> frag banks 8*t4+gid all distinct.
#define ASTR2 20
#define BSTR2 136
#define A_BUF (128 * ASTR2)
#define B_BUF (16 * BSTR2)
#define GEMM_SMEM ((4 * A_BUF + 4 * B_BUF) * 4)

__global__ void __launch_bounds__(256) gemm_tc(
    const float* __restrict__ A, const float* __restrict__ Bm,
    float* __restrict__ C, int M, int N, int K,
    const float* __restrict__ bias, int accum)
{
    extern __shared__ uint32_t smem[];
    uint32_t* AsH = smem;                     // [2][A_BUF]
    uint32_t* AsL = AsH + 2 * A_BUF;
    uint32_t* BsH = AsL + 2 * A_BUF;          // [2][B_BUF]
    uint32_t* BsL = BsH + 2 * B_BUF;

    const int tid = threadIdx.x;
    const int lane = tid & 31;
    const int warp = tid >> 5;
    const int warpM = warp >> 1;              // 0..3
    const int warpN = warp & 1;               // 0..1
    const int gid = lane >> 2;                // 0..7
    const int tid4 = lane & 3;                // 0..3

    const int m0 = blockIdx.y * 128;
    const int n0 = blockIdx.x * 128;

    const int a_row = tid >> 3;
    const int a_k4 = (tid & 7) * 4;
    const int b_n4 = lane * 4;

    float acc[2][8][4];
    #pragma unroll
    for (int i = 0; i < 2; i++)
        #pragma unroll
        for (int j = 0; j < 8; j++)
            #pragma unroll
            for (int c = 0; c < 4; c++) acc[i][j][c] = 0.f;

    float4 pa[4];
    float4 pb[4];
    const bool edge = (n0 + 128 > N);

    auto loadAB = [&](int kt) {
        const int kbase = kt * 32;
        #pragma unroll
        for (int i = 0; i < 4; i++)
            pa[i] = *reinterpret_cast<const float4*>(
                A + (size_t)(m0 + a_row + 32 * i) * K + kbase + a_k4);
        const int n = n0 + b_n4;
        #pragma unroll
        for (int i = 0; i < 2; i++) {
            const int kp = warp + 8 * i;
            #pragma unroll
            for (int r = 0; r < 2; r++) {
                const size_t off = (size_t)(kbase + 2 * kp + r) * N;
                float4 v;
                if (!edge) {
                    v = *reinterpret_cast<const float4*>(Bm + off + n);
                } else {
                    v.x = (n + 0 < N) ? Bm[off + n + 0] : 0.f;
                    v.y = (n + 1 < N) ? Bm[off + n + 1] : 0.f;
                    v.z = (n + 2 < N) ? Bm[off + n + 2] : 0.f;
                    v.w = (n + 3 < N) ? Bm[off + n + 3] : 0.f;
                }
                pb[2 * i + r] = v;
            }
        }
    };

    auto smemStore = [&](int buf) {
        uint32_t* ah = AsH + buf * A_BUF;
        uint32_t* al = AsL + buf * A_BUF;
        #pragma unroll
        for (int i = 0; i < 4; i++) {
            const int m = a_row + 32 * i;
            uint2 h2, l2;
            split_bf16_pair(pa[i].x, pa[i].y, h2.x, l2.x);
            split_bf16_pair(pa[i].z, pa[i].w, h2.y, l2.y);
            const int idx = m * ASTR2 + (a_k4 >> 1);
            *reinterpret_cast<uint2*>(ah + idx) = h2;
            *reinterpret_cast<uint2*>(al + idx) = l2;
        }
        uint32_t* bh = BsH + buf * B_BUF;
        uint32_t* bl = BsL + buf * B_BUF;
        #pragma unroll
        for (int i = 0; i < 2; i++) {
            const int kp = warp + 8 * i;
            const float4 r0 = pb[2 * i];
            const float4 r1 = pb[2 * i + 1];
            uint4 h4, l4;
            split_bf16_pair(r0.x, r1.x, h4.x, l4.x);
            split_bf16_pair(r0.y, r1.y, h4.y, l4.y);
            split_bf16_pair(r0.z, r1.z, h4.z, l4.z);
            split_bf16_pair(r0.w, r1.w, h4.w, l4.w);
            const int idx = kp * BSTR2 + b_n4;
            *reinterpret_cast<uint4*>(bh + idx) = h4;
            *reinterpret_cast<uint4*>(bl + idx) = l4;
        }
    };

    auto compute = [&](int buf) {
        const uint32_t* ah_s = AsH + buf * A_BUF;
        const uint32_t* al_s = AsL + buf * A_BUF;
        const uint32_t* bh_s = BsH + buf * B_BUF;
        const uint32_t* bl_s = BsL + buf * B_BUF;
        #pragma unroll
        for (int ks = 0; ks < 2; ks++) {
            const int kp0 = ks * 8;
            uint32_t ah[2][4], al[2][4], bh[8][2], bl[8][2];
            #pragma unroll
            for (int mf = 0; mf < 2; mf++) {
                const int m = warpM * 32 + mf * 16 + gid;
                const int i0 = m * ASTR2 + kp0 + tid4;
                const int i1 = (m + 8) * ASTR2 + kp0 + tid4;
                ah[mf][0] = ah_s[i0];     al[mf][0] = al_s[i0];
                ah[mf][1] = ah_s[i1];     al[mf][1] = al_s[i1];
                ah[mf][2] = ah_s[i0 + 4]; al[mf][2] = al_s[i0 + 4];
                ah[mf][3] = ah_s[i1 + 4]; al[mf][3] = al_s[i1 + 4];
            }
            #pragma unroll
            for (int nf = 0; nf < 8; nf++) {
                const int n = warpN * 64 + nf * 8 + gid;
                const int i0 = (kp0 + tid4) * BSTR2 + n;
                const int i1 = (kp0 + tid4 + 4) * BSTR2 + n;
                bh[nf][0] = bh_s[i0]; bl[nf][0] = bl_s[i0];
                bh[nf][1] = bh_s[i1]; bl[nf][1] = bl_s[i1];
            }
            #pragma unroll
            for (int mf = 0; mf < 2; mf++)
                #pragma unroll
                for (int nf = 0; nf < 8; nf++) {
                    mma_bf16(acc[mf][nf], ah[mf], bh[nf]);
                    mma_bf16(acc[mf][nf], al[mf], bh[nf]);
                    mma_bf16(acc[mf][nf], ah[mf], bl[nf]);
                }
        }
    };

    const int nk = K >> 5;
    loadAB(0);
    smemStore(0);
    __syncthreads();
    for (int kt = 0; kt < nk; kt++) {
        const int buf = kt & 1;
        if (kt + 1 < nk) loadAB(kt + 1);
        compute(buf);
        if (kt + 1 < nk) smemStore(buf ^ 1);
        __syncthreads();
    }

    // epilogue: C rows m, cols n..n+1 (float2)
    #pragma unroll
    for (int mf = 0; mf < 2; mf++) {
        #pragma unroll
        for (int nf = 0; nf < 8; nf++) {
            const int n = n0 + warpN * 64 + nf * 8 + tid4 * 2;
            if (n >= N) continue;
            float bv0 = 0.f, bv1 = 0.f;
            if (bias) { bv0 = bias[n]; bv1 = bias[n + 1]; }
            #pragma unroll
            for (int h = 0; h < 2; h++) {
                const int m = m0 + warpM * 32 + mf * 16 + gid + h * 8;
                float v0 = acc[mf][nf][2 * h]     + bv0;
                float v1 = acc[mf][nf][2 * h + 1] + bv1;
                const size_t idx = (size_t)m * N + n;
                if (accum) { v0 += C[idx]; v1 += C[idx + 1]; }
                C[idx] = v0;
                C[idx + 1] = v1;
            }
        }
    }
}

// ---------------- rmsnorm for D_=1024 rows, float4 vectorized ----------------
__global__ void __launch_bounds__(256) rmsnorm_kernel(
    const float* __restrict__ x, const float* __restrict__ w, float* __restrict__ out)
{
    int row = blockIdx.x;
    const float4* xr = reinterpret_cast<const float4*>(x + (size_t)row * D_);
    float4 v = xr[threadIdx.x];
    float ss = v.x * v.x + v.y * v.y + v.z * v.z + v.w * v.w;
    float tot = block_reduce_sum(ss);
    float r = rsqrtf(tot * (1.f / (float)D_) + 1e-6f);
    float4 wv = reinterpret_cast<const float4*>(w)[threadIdx.x];
    float4 o;
    o.x = v.x * r * wv.x; o.y = v.y * r * wv.y;
    o.z = v.z * r * wv.z; o.w = v.w * r * wv.w;
    reinterpret_cast<float4*>(out + (size_t)row * D_)[threadIdx.x] = o;
}

// ------- fused causal depthwise conv (K=3) + silu AND dt softplus (2-D grid) --
__global__ void convdt_kernel(const float* __restrict__ proj, const float* __restrict__ w,
                              const float* __restrict__ bias, float* __restrict__ out,
                              const float* __restrict__ dt_bias, float* __restrict__ dt_out)
{
    int c = blockIdx.x * 256 + threadIdx.x;
    int row = blockIdx.y;
    if (c < CONV_) {
        int t = row & (T_ - 1);
        const float* pr = proj + (size_t)row * PROJ_ + I_ + c;
        float acc = bias[c] + pr[0] * w[2 * CONV_ + c];
        if (t >= 1) acc += pr[-(ptrdiff_t)PROJ_] * w[CONV_ + c];
        if (t >= 2) acc += pr[-2 * (ptrdiff_t)PROJ_] * w[c];
        out[(size_t)row * CONV_ + c] = siluf(acc);
    } else if (c < CONV_ + H_) {
        int h = c - CONV_;
        float v = proj[(size_t)row * PROJ_ + I_ + CONV_ + h] + dt_bias[h];
        dt_out[(size_t)row * H_ + h] = (v > 20.f) ? v : log1pf(__expf(v));
    }
}

// ---------------- sequential SSM scan: one CTA per (b,h,n-half), unroll x2 ----
__global__ void __launch_bounds__(128) scan_kernel(
    const float* __restrict__ conv,   // [BT, CONV_]
    const float* __restrict__ dt,     // [BT, H_]
    const float* __restrict__ A_log,  // [H_]
    const float* __restrict__ Dv,     // [H_]
    float* __restrict__ y)            // [2][BT, I_] partials
{
    const int half = blockIdx.x >> 7;         // 0/1 -> n in [0,32) or [32,64)
    const int bh = blockIdx.x & 127;
    const int b = bh >> 4;
    const int h = bh & 15;
    const int p = threadIdx.x;
    const int n_off = half * 32;
    __shared__ float sB[2][32], sC[2][32];
    float a = -__expf(A_log[h]);
    float dcoef = (half == 0) ? Dv[h] : 0.f;
    float s[32];
    #pragma unroll
    for (int n = 0; n < 32; n++) s[n] = 0.f;

    const float* convb = conv + (size_t)b * T_ * CONV_;
    const float* dtb = dt + (size_t)b * T_ * H_ + h;
    float* yb = y + (size_t)half * BT * I_ + (size_t)b * T_ * I_ + h * P_ + p;

    for (int t = 0; t < T_; t += 2) {
        const float* crow0 = convb + (size_t)t * CONV_;
        const float* crow1 = crow0 + CONV_;
        if (p < 32)       { sB[0][p] = crow0[I_ + n_off + p];
                            sB[1][p] = crow1[I_ + n_off + p]; }
        else if (p < 64)  { sC[0][p - 32] = crow0[I_ + N_ + n_off + (p - 32)];
                            sC[1][p - 32] = crow1[I_ + N_ + n_off + (p - 32)]; }
        float dt0 = dtb[(size_t)t * H_];
        float dt1 = dtb[(size_t)(t + 1) * H_];
        float x0 = crow0[h * P_ + p];
        float x1 = crow1[h * P_ + p];
        __syncthreads();
        float dA0 = __expf(dt0 * a);
        float dA1 = __expf(dt1 * a);
        float k0 = dt0 * x0;
        float k1 = dt1 * x1;
        float y0a = 0.f, y0b = 0.f, y1a = 0.f, y1b = 0.f;
        #pragma unroll
        for (int n = 0; n < 32; n += 2) {
            s[n]     = s[n]     * dA0 + k0 * sB[0][n];     y0a += s[n]     * sC[0][n];
            s[n + 1] = s[n + 1] * dA0 + k0 * sB[0][n + 1]; y0b += s[n + 1] * sC[0][n + 1];
            s[n]     = s[n]     * dA1 + k1 * sB[1][n];     y1a += s[n]     * sC[1][n];
            s[n + 1] = s[n + 1] * dA1 + k1 * sB[1][n + 1]; y1b += s[n + 1] * sC[1][n + 1];
        }
        yb[(size_t)t * I_]       = y0a + y0b + dcoef * x0;
        yb[(size_t)(t + 1) * I_] = y1a + y1b + dcoef * x1;
        __syncthreads();
    }
}

// ------- gated rmsnorm: y = rmsnorm((y0+y1) * silu(gate)) * w, float4 ---------
__global__ void __launch_bounds__(256) grms_kernel(
    float* __restrict__ yout, const float* __restrict__ y0p, const float* __restrict__ y1p,
    const float* __restrict__ proj, const float* __restrict__ w)
{
    int row = blockIdx.x;
    const float4* y0r = reinterpret_cast<const float4*>(y0p + (size_t)row * I_);
    const float4* y1r = reinterpret_cast<const float4*>(y1p + (size_t)row * I_);
    const float4* gr = reinterpret_cast<const float4*>(proj + (size_t)row * PROJ_);
    float4 v[2];
    float ss = 0.f;
    #pragma unroll
    for (int k = 0; k < 2; k++) {
        int i = threadIdx.x + k * 256;
        float4 a = y0r[i], b = y1r[i], g = gr[i];
        v[k].x = (a.x + b.x) * siluf(g.x);
        v[k].y = (a.y + b.y) * siluf(g.y);
        v[k].z = (a.z + b.z) * siluf(g.z);
        v[k].w = (a.w + b.w) * siluf(g.w);
        ss += v[k].x * v[k].x + v[k].y * v[k].y + v[k].z * v[k].z + v[k].w * v[k].w;
    }
    float tot = block_reduce_sum(ss);
    float r = rsqrtf(tot * (1.f / (float)I_) + 1e-6f);
    #pragma unroll
    for (int k = 0; k < 2; k++) {
        int i = threadIdx.x + k * 256;
        float4 wv = reinterpret_cast<const float4*>(w)[i];
        float4 o;
        o.x = v[k].x * r * wv.x; o.y = v[k].y * r * wv.y;
        o.z = v[k].z * r * wv.z; o.w = v[k].w * r * wv.w;
        reinterpret_cast<float4*>(yout + (size_t)row * I_)[i] = o;
    }
}

// ---------------- host launcher ----------------
extern "C" void kernel_launch(void* const* d_in, const int* in_sizes, int n_in,
                              void* d_out, int out_size)
{
    const float* x        = (const float*)d_in[0];
    const float* in_w     = (const float*)d_in[1];
    const float* in_b     = (const float*)d_in[2];
    const float* norm_w   = (const float*)d_in[3];
    const float* mix_in_w = (const float*)d_in[4];
    const float* conv_w   = (const float*)d_in[5];
    const float* conv_b   = (const float*)d_in[6];
    const float* dt_bias  = (const float*)d_in[7];
    const float* A_log    = (const float*)d_in[8];
    const float* Dvec     = (const float*)d_in[9];
    const float* gnorm_w  = (const float*)d_in[10];
    const float* mix_out_w= (const float*)d_in[11];
    const float* out_w    = (const float*)d_in[12];
    const float* out_b    = (const float*)d_in[13];
    const float* code_w   = (const float*)d_in[14];
    const float* code_b   = (const float*)d_in[15];
    float* out = (float*)d_out;

    float *h, *hn, *proj, *conv, *dtb, *yb;
    cudaGetSymbolAddress((void**)&h,    g_h);
    cudaGetSymbolAddress((void**)&hn,   g_hn);
    cudaGetSymbolAddress((void**)&proj, g_proj);
    cudaGetSymbolAddress((void**)&conv, g_conv);
    cudaGetSymbolAddress((void**)&dtb,  g_dt);
    cudaGetSymbolAddress((void**)&yb,   g_y);
    float* yb0 = yb;
    float* yb1 = yb + (size_t)BT * I_;

    cudaFuncSetAttribute(gemm_tc, cudaFuncAttributeMaxDynamicSharedMemorySize, GEMM_SMEM);

    // h = x @ in_w + in_b
    gemm_tc<<<dim3(D_ / 128, BT / 128), 256, GEMM_SMEM>>>(x, in_w, h, BT, D_, IN_, in_b, 0);

    for (int l = 0; l < L_; l++) {
        rmsnorm_kernel<<<BT, 256>>>(h, norm_w + l * D_, hn);
        gemm_tc<<<dim3((PROJ_ + 127) / 128, BT / 128), 256, GEMM_SMEM>>>(
            hn, mix_in_w + (size_t)l * D_ * PROJ_, proj, BT, PROJ_, D_, nullptr, 0);
        convdt_kernel<<<dim3((CONV_ + H_ + 255) / 256, BT), 256>>>(
            proj, conv_w + (size_t)l * K_ * CONV_, conv_b + (size_t)l * CONV_, conv,
            dt_bias + l * H_, dtb);
        scan_kernel<<<2 * B_ * H_, 128>>>(conv, dtb, A_log + l * H_, Dvec + l * H_, yb);
        grms_kernel<<<BT, 256>>>(yb0, yb0, yb1, proj, gnorm_w + (size_t)l * I_);
        gemm_tc<<<dim3(D_ / 128, BT / 128), 256, GEMM_SMEM>>>(
            yb0, mix_out_w + (size_t)l * I_ * D_, h, BT, D_, I_, nullptr, 1);
    }

    // heads
    gemm_tc<<<dim3(OUT_ / 128, BT / 128), 256, GEMM_SMEM>>>(h, out_w, out, BT, OUT_, D_, out_b, 0);
    gemm_tc<<<dim3(CB_ / 128, BT / 128), 256, GEMM_SMEM>>>(
        h, code_w, out + (size_t)BT * OUT_, BT, CB_, D_, code_b, 0);
}